// round 6
// baseline (speedup 1.0000x reference)
#include <cuda_runtime.h>
#include <math.h>

// Problem constants (fixed by the reference)
#define NATOMS     8192
#define MAX_PAIRS  (64 * 8192)     // 524288
#define CUT2       25.0f           // cutoff_upper^2; cutoff_lower = 0
#define NCELL1     9               // 45.0 / 5.0
#define NCELLS     (NCELL1 * NCELL1 * NCELL1)   // 729
#define CAP        48              // bucket capacity (Poisson mean 11.2)
#define MASK_WORDS 256             // 8192 bits per row
#define NBLK       1024            // pairs grid: 8 rows (warps) per block
#define FULLMASK   0xffffffffu

// Scratch (device globals; zeroed by prefill_kernel at the start of every run)
__device__ int      g_cell_cnt[NCELLS];
__device__ float4   g_bpos[NCELLS * CAP];    // (x, y, z, atom_idx bits)
__device__ int      g_bbatch[NCELLS * CAP];
__device__ unsigned g_state[NBLK];           // decoupled-lookback state

// d2 with the SAME rounding as the reference: rounded products, then ((a+b)+c).
__device__ __forceinline__ float d2_exact(float dx, float dy, float dz) {
    float a = __fmul_rn(dx, dx);
    float b = __fmul_rn(dy, dy);
    float c = __fmul_rn(dz, dz);
    return __fadd_rn(__fadd_rn(a, b), c);
}

__device__ __forceinline__ int cell_coord(float p) {
    int c = (int)(p * 0.2f);
    return c < 0 ? 0 : (c > NCELL1 - 1 ? NCELL1 - 1 : c);
}

// ---------------------------------------------------------------------------
// K1: prefill output with defaults (pairs later overwrites the valid prefix)
// and zero the scratch state. Layout (floats): [0,2MP)=edge_index -> -1,
// [2MP,6MP)=weight+vec -> 0. Region boundary is float4-aligned.
// ---------------------------------------------------------------------------
__global__ void prefill_kernel(float4* __restrict__ out4) {
    const int idx = blockIdx.x * blockDim.x + threadIdx.x;   // 786432 threads
    const int idx4 = (2 * MAX_PAIRS) / 4;                    // 262144
    const float v = (idx < idx4) ? -1.0f : 0.0f;
    out4[idx] = make_float4(v, v, v, v);

    if (blockIdx.x == 0) {
        for (int k = threadIdx.x; k < NCELLS; k += blockDim.x) g_cell_cnt[k] = 0;
    } else if (blockIdx.x == 1) {
        for (int k = threadIdx.x; k < NBLK; k += blockDim.x) g_state[k] = 0u;
    }
}

// ---------------------------------------------------------------------------
// K2: bucketed cell-list build. One thread per atom, wide grid for MLP.
// ---------------------------------------------------------------------------
__global__ void build_kernel(const float* __restrict__ pos,
                             const int*   __restrict__ batch) {
    const int i = blockIdx.x * blockDim.x + threadIdx.x;
    if (i >= NATOMS) return;
    const float x = pos[3 * i + 0];
    const float y = pos[3 * i + 1];
    const float z = pos[3 * i + 2];
    const int c = cell_coord(x) * 81 + cell_coord(y) * 9 + cell_coord(z);
    const int slot = atomicAdd(&g_cell_cnt[c], 1);
    if (slot < CAP) {
        g_bpos[c * CAP + slot]   = make_float4(x, y, z, __int_as_float(i));
        g_bbatch[c * CAP + slot] = batch[i];
    }
}

// ---------------------------------------------------------------------------
// K3: fused count + global scan (decoupled lookback) + ordered write.
// One warp per row i, 8 rows per block. Per (ix,iy) strip, lanes are
// partitioned across the 2-3 z-cells; 2 candidates per lane per iteration
// (s and s+32) so two L2 loads are in flight per lane.
// Row bitmask in shared gives exact row-major (i, ascending-j) order.
// ---------------------------------------------------------------------------
__global__ void pairs_kernel(const float* __restrict__ pos,
                             const int*   __restrict__ batch,
                             float*       __restrict__ out) {
    __shared__ unsigned smask[8][MASK_WORDS];
    __shared__ int scnt[8];
    __shared__ int srowoff[8];
    const int warp = threadIdx.x >> 5;
    const int lane = threadIdx.x & 31;
    const int b = blockIdx.x;
    const int i = b * 8 + warp;

    for (int k = lane; k < MASK_WORDS; k += 32) smask[warp][k] = 0;

    const float pix = pos[3 * i + 0];
    const float piy = pos[3 * i + 1];
    const float piz = pos[3 * i + 2];
    const int   bi  = batch[i];
    __syncwarp();

    const int cx = cell_coord(pix), cy = cell_coord(piy), cz = cell_coord(piz);
    const int x0 = max(cx - 1, 0), x1 = min(cx + 1, NCELL1 - 1);
    const int y0 = max(cy - 1, 0), y1 = min(cy + 1, NCELL1 - 1);
    const int z0 = max(cz - 1, 0), z1 = min(cz + 1, NCELL1 - 1);
    const int nz = z1 - z0;                    // 1 or 2 extra cells beyond c0

    unsigned* __restrict__ mask = smask[warp];

    for (int ix = x0; ix <= x1; ix++) {
        for (int iy = y0; iy <= y1; iy++) {
            const int c0 = ix * 81 + iy * 9 + z0;
            int n0 = g_cell_cnt[c0];                      n0 = n0 > CAP ? CAP : n0;
            int n1 = (nz >= 1) ? g_cell_cnt[c0 + 1] : 0;  n1 = n1 > CAP ? CAP : n1;
            int n2 = (nz >= 2) ? g_cell_cnt[c0 + 2] : 0;  n2 = n2 > CAP ? CAP : n2;
            const int n01 = n0 + n1;
            const int tot = n01 + n2;
            const int base0 = c0 * CAP;

            for (int s = lane; s < tot; s += 64) {
                // candidate A (always valid)
                const int sA = s;
                int ccA, offA;
                if (sA < n0)       { ccA = 0; offA = sA; }
                else if (sA < n01) { ccA = 1; offA = sA - n0; }
                else               { ccA = 2; offA = sA - n01; }
                const int slotA = base0 + ccA * CAP + offA;

                // candidate B (maybe invalid)
                const int sB = s + 32;
                const bool hasB = (sB < tot);
                int ccB, offB;
                if (sB < n0)       { ccB = 0; offB = sB; }
                else if (sB < n01) { ccB = 1; offB = sB - n0; }
                else               { ccB = 2; offB = sB - n01; }
                const int slotB = hasB ? (base0 + ccB * CAP + offB) : slotA;

                // issue both loads before consuming either
                const float4 pA = g_bpos[slotA];
                const float4 pB = g_bpos[slotB];

                {
                    const float dx = pix - pA.x;
                    const float dy = piy - pA.y;
                    const float dz = piz - pA.z;
                    const float d2 = d2_exact(dx, dy, dz);
                    const int j = __float_as_int(pA.w);
                    if (d2 < CUT2 && j != i) {
                        if (g_bbatch[slotA] == bi)
                            atomicOr(&mask[j >> 5], 1u << (j & 31));
                    }
                }
                if (hasB) {
                    const float dx = pix - pB.x;
                    const float dy = piy - pB.y;
                    const float dz = piz - pB.z;
                    const float d2 = d2_exact(dx, dy, dz);
                    const int j = __float_as_int(pB.w);
                    if (d2 < CUT2 && j != i) {
                        if (g_bbatch[slotB] == bi)
                            atomicOr(&mask[j >> 5], 1u << (j & 31));
                    }
                }
            }
        }
    }
    __syncwarp();

    // per-row count from the mask
    int cnt = 0;
    #pragma unroll
    for (int k = 0; k < 8; k++) cnt += __popc(mask[lane * 8 + k]);
    cnt = __reduce_add_sync(FULLMASK, cnt);
    if (lane == 0) scnt[warp] = cnt;
    __syncthreads();

    // warp 0: publish aggregate, decoupled lookback, publish inclusive prefix
    if (warp == 0) {
        int agg = 0;
        if (lane == 0) {
            #pragma unroll
            for (int r = 0; r < 8; r++) agg += scnt[r];
            atomicExch(&g_state[b], (1u << 30) | (unsigned)agg);
        }
        agg = __shfl_sync(FULLMASK, agg, 0);

        int excl = 0;
        int look = b - 1;
        bool done = (look < 0);
        while (!done) {
            const int idx = look - lane;
            unsigned v;
            if (idx >= 0) {
                do { v = *(volatile unsigned*)&g_state[idx]; } while (v == 0u);
            } else {
                v = (2u << 30);               // virtual PREFIX=0 before block 0
            }
            const unsigned flag = v >> 30;
            const int val = (int)(v & 0x3FFFFFFFu);
            const unsigned pmask = __ballot_sync(FULLMASK, flag == 2u);
            const int limit = (pmask != 0u) ? (__ffs(pmask) - 1) : 31;
            int contrib = (lane <= limit) ? val : 0;
            #pragma unroll
            for (int d = 16; d > 0; d >>= 1)
                contrib += __shfl_down_sync(FULLMASK, contrib, d);
            contrib = __shfl_sync(FULLMASK, contrib, 0);
            excl += contrib;
            if (pmask != 0u) done = true; else look -= 32;
        }
        if (lane == 0) {
            atomicExch(&g_state[b], (2u << 30) | (unsigned)(excl + agg));
            int run = excl;
            #pragma unroll
            for (int r = 0; r < 8; r++) { srowoff[r] = run; run += scnt[r]; }
        }
    }
    __syncthreads();

    // ordered write: lane l owns words [8l, 8l+8) -> j in [256l, 256(l+1))
    unsigned w8[8];
    #pragma unroll
    for (int t = 0; t < 8; t++) w8[t] = mask[lane * 8 + t];

    int myc = 0;
    #pragma unroll
    for (int t = 0; t < 8; t++) myc += __popc(w8[t]);

    int incl = myc;
    #pragma unroll
    for (int d = 1; d < 32; d <<= 1) {
        int u = __shfl_up_sync(FULLMASK, incl, d);
        if (lane >= d) incl += u;
    }
    int p = srowoff[warp] + incl - myc;

    const float fi = (float)i;
    float* __restrict__ outI = out;
    float* __restrict__ outJ = out + MAX_PAIRS;
    float* __restrict__ outW = out + 2 * MAX_PAIRS;
    float* __restrict__ outV = out + 3 * MAX_PAIRS;

    #pragma unroll
    for (int t = 0; t < 8; t++) {
        unsigned word = w8[t];
        const int jbase = (lane * 8 + t) * 32;
        while (word) {
            const int bpos = __ffs(word) - 1;
            word &= word - 1;
            const int j = jbase + bpos;
            const float dx = pix - pos[3 * j + 0];
            const float dy = piy - pos[3 * j + 1];
            const float dz = piz - pos[3 * j + 2];
            const float d2 = d2_exact(dx, dy, dz);
            if (p < MAX_PAIRS) {
                outI[p] = fi;
                outJ[p] = (float)j;
                outW[p] = sqrtf(d2);
                outV[3 * p + 0] = dx;
                outV[3 * p + 1] = dy;
                outV[3 * p + 2] = dz;
            }
            p++;
        }
    }
}

// ---------------------------------------------------------------------------
extern "C" void kernel_launch(void* const* d_in, const int* in_sizes, int n_in,
                              void* d_out, int out_size) {
    const float* pos   = (const float*)d_in[0];   // [8192, 3] f32
    const int*   batch = (const int*)d_in[1];     // [8192] i32
    float* out = (float*)d_out;                   // 6 * MAX_PAIRS floats

    (void)in_sizes; (void)n_in; (void)out_size;

    // 786432 float4 = 12.58 MB of defaults
    prefill_kernel<<<3072, 256>>>((float4*)out);
    build_kernel<<<NATOMS / 64, 64>>>(pos, batch);
    pairs_kernel<<<NBLK, 256>>>(pos, batch, out);
}

// round 7
// speedup vs baseline: 1.2041x; 1.2041x over previous
#include <cuda_runtime.h>
#include <math.h>

// Problem constants (fixed by the reference)
#define NATOMS     8192
#define MAX_PAIRS  (64 * 8192)     // 524288
#define CUT2       25.0f           // cutoff_upper^2; cutoff_lower = 0
#define NCELL1     9               // 45.0 / 5.0
#define NCELLS     (NCELL1 * NCELL1 * NCELL1)   // 729
#define CAP        48              // bucket capacity (Poisson mean 11.2)
#define MASK_WORDS 256             // 8192 bits per row
#define NBLK       1024            // pairs grid: 8 rows (warps) per block
#define FULLMASK   0xffffffffu

// Scratch (device globals)
__device__ int      g_cell_cnt[NCELLS];
__device__ float4   g_bpos[NCELLS * CAP];    // (x, y, z, atom_idx bits)
__device__ int      g_bbatch[NCELLS * CAP];
__device__ unsigned g_state[NBLK];           // decoupled-lookback state
__device__ int      g_total;

// d2 with the SAME rounding as the reference: rounded products, then ((a+b)+c).
__device__ __forceinline__ float d2_exact(float dx, float dy, float dz) {
    float a = __fmul_rn(dx, dx);
    float b = __fmul_rn(dy, dy);
    float c = __fmul_rn(dz, dz);
    return __fadd_rn(__fadd_rn(a, b), c);
}

__device__ __forceinline__ int cell_coord(float p) {
    int c = (int)(p * 0.2f);
    return c < 0 ? 0 : (c > NCELL1 - 1 ? NCELL1 - 1 : c);
}

// ---------------------------------------------------------------------------
// K0: zero scratch (tiny, ~1us).
// ---------------------------------------------------------------------------
__global__ void zero_kernel() {
    const int t = threadIdx.x;
    if (t < NCELLS) g_cell_cnt[t] = 0;
    g_state[t] = 0u;
}

// ---------------------------------------------------------------------------
// K1: bucketed cell-list build. One thread per atom, wide grid for latency.
// ---------------------------------------------------------------------------
__global__ void build_kernel(const float* __restrict__ pos,
                             const int*   __restrict__ batch) {
    const int i = blockIdx.x * blockDim.x + threadIdx.x;
    if (i >= NATOMS) return;
    const float x = pos[3 * i + 0];
    const float y = pos[3 * i + 1];
    const float z = pos[3 * i + 2];
    const int c = cell_coord(x) * 81 + cell_coord(y) * 9 + cell_coord(z);
    const int slot = atomicAdd(&g_cell_cnt[c], 1);
    if (slot < CAP) {
        g_bpos[c * CAP + slot]   = make_float4(x, y, z, __int_as_float(i));
        g_bbatch[c * CAP + slot] = batch[i];
    }
}

// ---------------------------------------------------------------------------
// K2: fused count + global scan (decoupled lookback) + ordered write.
// One warp per row i, 8 rows per block. Per (ix,iy) strip, lanes are
// partitioned across the 2-3 z-cells. Row bitmask in shared gives exact
// row-major (i, ascending-j) order.  (R5-proven inner loop.)
// ---------------------------------------------------------------------------
__global__ void pairs_kernel(const float* __restrict__ pos,
                             const int*   __restrict__ batch,
                             float*       __restrict__ out) {
    __shared__ unsigned smask[8][MASK_WORDS];
    __shared__ int scnt[8];
    __shared__ int srowoff[8];
    const int warp = threadIdx.x >> 5;
    const int lane = threadIdx.x & 31;
    const int b = blockIdx.x;
    const int i = b * 8 + warp;

    for (int k = lane; k < MASK_WORDS; k += 32) smask[warp][k] = 0;

    const float pix = pos[3 * i + 0];
    const float piy = pos[3 * i + 1];
    const float piz = pos[3 * i + 2];
    const int   bi  = batch[i];
    __syncwarp();

    const int cx = cell_coord(pix), cy = cell_coord(piy), cz = cell_coord(piz);
    const int x0 = max(cx - 1, 0), x1 = min(cx + 1, NCELL1 - 1);
    const int y0 = max(cy - 1, 0), y1 = min(cy + 1, NCELL1 - 1);
    const int z0 = max(cz - 1, 0), z1 = min(cz + 1, NCELL1 - 1);
    const int nz = z1 - z0;                    // 1 or 2 extra cells beyond c0

    unsigned* __restrict__ mask = smask[warp];

    for (int ix = x0; ix <= x1; ix++) {
        for (int iy = y0; iy <= y1; iy++) {
            const int c0 = ix * 81 + iy * 9 + z0;
            int n0 = g_cell_cnt[c0];                      n0 = n0 > CAP ? CAP : n0;
            int n1 = (nz >= 1) ? g_cell_cnt[c0 + 1] : 0;  n1 = n1 > CAP ? CAP : n1;
            int n2 = (nz >= 2) ? g_cell_cnt[c0 + 2] : 0;  n2 = n2 > CAP ? CAP : n2;
            const int n01 = n0 + n1;
            const int tot = n01 + n2;
            for (int s = lane; s < tot; s += 32) {
                int cc, off;
                if (s < n0)       { cc = c0;     off = s; }
                else if (s < n01) { cc = c0 + 1; off = s - n0; }
                else              { cc = c0 + 2; off = s - n01; }
                const int slot = cc * CAP + off;
                const float4 pj = g_bpos[slot];
                const float dx = pix - pj.x;
                const float dy = piy - pj.y;
                const float dz = piz - pj.z;
                const float d2 = d2_exact(dx, dy, dz);
                const int j = __float_as_int(pj.w);
                if (d2 < CUT2 && j != i && g_bbatch[slot] == bi) {
                    atomicOr(&mask[j >> 5], 1u << (j & 31));
                }
            }
        }
    }
    __syncwarp();

    // per-row count from the mask
    int cnt = 0;
    #pragma unroll
    for (int k = 0; k < 8; k++) cnt += __popc(mask[lane * 8 + k]);
    cnt = __reduce_add_sync(FULLMASK, cnt);
    if (lane == 0) scnt[warp] = cnt;
    __syncthreads();

    // warp 0: publish aggregate, decoupled lookback, publish inclusive prefix
    if (warp == 0) {
        int agg = 0;
        if (lane == 0) {
            #pragma unroll
            for (int r = 0; r < 8; r++) agg += scnt[r];
            atomicExch(&g_state[b], (1u << 30) | (unsigned)agg);
        }
        agg = __shfl_sync(FULLMASK, agg, 0);

        int excl = 0;
        int look = b - 1;
        bool done = (look < 0);
        while (!done) {
            const int idx = look - lane;
            unsigned v;
            if (idx >= 0) {
                do { v = *(volatile unsigned*)&g_state[idx]; } while (v == 0u);
            } else {
                v = (2u << 30);               // virtual PREFIX=0 before block 0
            }
            const unsigned flag = v >> 30;
            const int val = (int)(v & 0x3FFFFFFFu);
            const unsigned pmask = __ballot_sync(FULLMASK, flag == 2u);
            const int limit = (pmask != 0u) ? (__ffs(pmask) - 1) : 31;
            int contrib = (lane <= limit) ? val : 0;
            #pragma unroll
            for (int d = 16; d > 0; d >>= 1)
                contrib += __shfl_down_sync(FULLMASK, contrib, d);
            contrib = __shfl_sync(FULLMASK, contrib, 0);
            excl += contrib;
            if (pmask != 0u) done = true; else look -= 32;
        }
        if (lane == 0) {
            atomicExch(&g_state[b], (2u << 30) | (unsigned)(excl + agg));
            if (b == NBLK - 1) g_total = excl + agg;
            int run = excl;
            #pragma unroll
            for (int r = 0; r < 8; r++) { srowoff[r] = run; run += scnt[r]; }
        }
    }
    __syncthreads();

    // ordered write: lane l owns words [8l, 8l+8) -> j in [256l, 256(l+1))
    unsigned w8[8];
    #pragma unroll
    for (int t = 0; t < 8; t++) w8[t] = mask[lane * 8 + t];

    int myc = 0;
    #pragma unroll
    for (int t = 0; t < 8; t++) myc += __popc(w8[t]);

    int incl = myc;
    #pragma unroll
    for (int d = 1; d < 32; d <<= 1) {
        int u = __shfl_up_sync(FULLMASK, incl, d);
        if (lane >= d) incl += u;
    }
    int p = srowoff[warp] + incl - myc;

    const float fi = (float)i;
    float* __restrict__ outI = out;
    float* __restrict__ outJ = out + MAX_PAIRS;
    float* __restrict__ outW = out + 2 * MAX_PAIRS;
    float* __restrict__ outV = out + 3 * MAX_PAIRS;

    #pragma unroll
    for (int t = 0; t < 8; t++) {
        unsigned word = w8[t];
        const int jbase = (lane * 8 + t) * 32;
        while (word) {
            const int bpos = __ffs(word) - 1;
            word &= word - 1;
            const int j = jbase + bpos;
            const float dx = pix - pos[3 * j + 0];
            const float dy = piy - pos[3 * j + 1];
            const float dz = piz - pos[3 * j + 2];
            const float d2 = d2_exact(dx, dy, dz);
            if (p < MAX_PAIRS) {
                outI[p] = fi;
                outJ[p] = (float)j;
                outW[p] = sqrtf(d2);
                outV[3 * p + 0] = dx;
                outV[3 * p + 1] = dy;
                outV[3 * p + 2] = dz;
            }
            p++;
        }
    }
}

// ---------------------------------------------------------------------------
// K3: tail fill. Thread t handles slot p = g_total + t; only the ~invalid
// tail does work (6 stores per slot), everything else exits immediately.
// ---------------------------------------------------------------------------
__global__ void tailfix_kernel(float* __restrict__ out) {
    int total = g_total;
    if (total > MAX_PAIRS) total = MAX_PAIRS;
    const int p = total + blockIdx.x * blockDim.x + threadIdx.x;
    if (p >= MAX_PAIRS) return;
    out[p]                 = -1.0f;   // edge_index i
    out[MAX_PAIRS + p]     = -1.0f;   // edge_index j
    out[2 * MAX_PAIRS + p] = 0.0f;    // edge_weight
    float* v = out + 3 * MAX_PAIRS + 3 * p;
    v[0] = 0.0f; v[1] = 0.0f; v[2] = 0.0f;
}

// ---------------------------------------------------------------------------
extern "C" void kernel_launch(void* const* d_in, const int* in_sizes, int n_in,
                              void* d_out, int out_size) {
    const float* pos   = (const float*)d_in[0];   // [8192, 3] f32
    const int*   batch = (const int*)d_in[1];     // [8192] i32
    float* out = (float*)d_out;                   // 6 * MAX_PAIRS floats

    (void)in_sizes; (void)n_in; (void)out_size;

    zero_kernel<<<1, 1024>>>();
    build_kernel<<<NATOMS / 64, 64>>>(pos, batch);
    pairs_kernel<<<NBLK, 256>>>(pos, batch, out);
    tailfix_kernel<<<MAX_PAIRS / 256, 256>>>(out);
}

// round 8
// speedup vs baseline: 1.2807x; 1.0636x over previous
#include <cuda_runtime.h>
#include <math.h>

// Problem constants (fixed by the reference)
#define NATOMS     8192
#define MAX_PAIRS  (64 * 8192)     // 524288
#define CUT2       25.0f           // cutoff_upper^2; cutoff_lower = 0
#define NCELL1     9               // 45.0 / 5.0
#define NCELLS     (NCELL1 * NCELL1 * NCELL1)   // 729
#define CAP        48              // bucket capacity (Poisson mean 11.2)
#define MASK_WORDS 256             // 8192 bits per row
#define NBLK       1024            // pairs grid: 8 rows (warps) per block
#define FULLMASK   0xffffffffu

// Scratch (device globals; zero at module load, re-zeroed by tailfix_kernel
// at the END of every run so each graph replay starts from clean state)
__device__ int      g_cell_cnt[NCELLS];
__device__ float4   g_bpos[NCELLS * CAP];    // (x, y, z, atom_idx bits)
__device__ int      g_bbatch[NCELLS * CAP];
__device__ unsigned g_state[NBLK];           // decoupled-lookback state
__device__ int      g_total;

// d2 with the SAME rounding as the reference: rounded products, then ((a+b)+c).
__device__ __forceinline__ float d2_exact(float dx, float dy, float dz) {
    float a = __fmul_rn(dx, dx);
    float b = __fmul_rn(dy, dy);
    float c = __fmul_rn(dz, dz);
    return __fadd_rn(__fadd_rn(a, b), c);
}

__device__ __forceinline__ int cell_coord(float p) {
    int c = (int)(p * 0.2f);
    return c < 0 ? 0 : (c > NCELL1 - 1 ? NCELL1 - 1 : c);
}

// ---------------------------------------------------------------------------
// K1: bucketed cell-list build. One thread per atom, wide grid for latency.
// g_cell_cnt arrives zeroed (load-time init / restored by K3 last run).
// ---------------------------------------------------------------------------
__global__ void build_kernel(const float* __restrict__ pos,
                             const int*   __restrict__ batch) {
    const int i = blockIdx.x * blockDim.x + threadIdx.x;
    if (i >= NATOMS) return;
    const float x = pos[3 * i + 0];
    const float y = pos[3 * i + 1];
    const float z = pos[3 * i + 2];
    const int c = cell_coord(x) * 81 + cell_coord(y) * 9 + cell_coord(z);
    const int slot = atomicAdd(&g_cell_cnt[c], 1);
    if (slot < CAP) {
        g_bpos[c * CAP + slot]   = make_float4(x, y, z, __int_as_float(i));
        g_bbatch[c * CAP + slot] = batch[i];
    }
}

// ---------------------------------------------------------------------------
// K2: fused count + global scan (decoupled lookback) + ordered write.
// One warp per row i, 8 rows per block. Per (ix,iy) strip, lanes are
// partitioned across the 2-3 z-cells. Row bitmask in shared gives exact
// row-major (i, ascending-j) order.
// ---------------------------------------------------------------------------
__global__ void pairs_kernel(const float* __restrict__ pos,
                             const int*   __restrict__ batch,
                             float*       __restrict__ out) {
    __shared__ unsigned smask[8][MASK_WORDS];
    __shared__ int scnt[8];
    __shared__ int srowoff[8];
    const int warp = threadIdx.x >> 5;
    const int lane = threadIdx.x & 31;
    const int b = blockIdx.x;
    const int i = b * 8 + warp;

    for (int k = lane; k < MASK_WORDS; k += 32) smask[warp][k] = 0;

    const float pix = pos[3 * i + 0];
    const float piy = pos[3 * i + 1];
    const float piz = pos[3 * i + 2];
    const int   bi  = batch[i];
    __syncwarp();

    const int cx = cell_coord(pix), cy = cell_coord(piy), cz = cell_coord(piz);
    const int x0 = max(cx - 1, 0), x1 = min(cx + 1, NCELL1 - 1);
    const int y0 = max(cy - 1, 0), y1 = min(cy + 1, NCELL1 - 1);
    const int z0 = max(cz - 1, 0), z1 = min(cz + 1, NCELL1 - 1);
    const int nz = z1 - z0;                    // 1 or 2 extra cells beyond c0

    unsigned* __restrict__ mask = smask[warp];

    for (int ix = x0; ix <= x1; ix++) {
        for (int iy = y0; iy <= y1; iy++) {
            const int c0 = ix * 81 + iy * 9 + z0;
            int n0 = g_cell_cnt[c0];                      n0 = n0 > CAP ? CAP : n0;
            int n1 = (nz >= 1) ? g_cell_cnt[c0 + 1] : 0;  n1 = n1 > CAP ? CAP : n1;
            int n2 = (nz >= 2) ? g_cell_cnt[c0 + 2] : 0;  n2 = n2 > CAP ? CAP : n2;
            const int n01 = n0 + n1;
            const int tot = n01 + n2;
            for (int s = lane; s < tot; s += 32) {
                int cc, off;
                if (s < n0)       { cc = c0;     off = s; }
                else if (s < n01) { cc = c0 + 1; off = s - n0; }
                else              { cc = c0 + 2; off = s - n01; }
                const int slot = cc * CAP + off;
                const float4 pj = g_bpos[slot];
                const float dx = pix - pj.x;
                const float dy = piy - pj.y;
                const float dz = piz - pj.z;
                const float d2 = d2_exact(dx, dy, dz);
                const int j = __float_as_int(pj.w);
                if (d2 < CUT2 && j != i && g_bbatch[slot] == bi) {
                    atomicOr(&mask[j >> 5], 1u << (j & 31));
                }
            }
        }
    }
    __syncwarp();

    // per-row count from the mask
    int cnt = 0;
    #pragma unroll
    for (int k = 0; k < 8; k++) cnt += __popc(mask[lane * 8 + k]);
    cnt = __reduce_add_sync(FULLMASK, cnt);
    if (lane == 0) scnt[warp] = cnt;
    __syncthreads();

    // warp 0: publish aggregate, decoupled lookback, publish inclusive prefix
    if (warp == 0) {
        int agg = 0;
        if (lane == 0) {
            #pragma unroll
            for (int r = 0; r < 8; r++) agg += scnt[r];
            atomicExch(&g_state[b], (1u << 30) | (unsigned)agg);
        }
        agg = __shfl_sync(FULLMASK, agg, 0);

        int excl = 0;
        int look = b - 1;
        bool done = (look < 0);
        while (!done) {
            const int idx = look - lane;
            unsigned v;
            if (idx >= 0) {
                do { v = *(volatile unsigned*)&g_state[idx]; } while (v == 0u);
            } else {
                v = (2u << 30);               // virtual PREFIX=0 before block 0
            }
            const unsigned flag = v >> 30;
            const int val = (int)(v & 0x3FFFFFFFu);
            const unsigned pmask = __ballot_sync(FULLMASK, flag == 2u);
            const int limit = (pmask != 0u) ? (__ffs(pmask) - 1) : 31;
            int contrib = (lane <= limit) ? val : 0;
            #pragma unroll
            for (int d = 16; d > 0; d >>= 1)
                contrib += __shfl_down_sync(FULLMASK, contrib, d);
            contrib = __shfl_sync(FULLMASK, contrib, 0);
            excl += contrib;
            if (pmask != 0u) done = true; else look -= 32;
        }
        if (lane == 0) {
            atomicExch(&g_state[b], (2u << 30) | (unsigned)(excl + agg));
            if (b == NBLK - 1) g_total = excl + agg;
            int run = excl;
            #pragma unroll
            for (int r = 0; r < 8; r++) { srowoff[r] = run; run += scnt[r]; }
        }
    }
    __syncthreads();

    // ordered write: lane l owns words [8l, 8l+8) -> j in [256l, 256(l+1))
    unsigned w8[8];
    #pragma unroll
    for (int t = 0; t < 8; t++) w8[t] = mask[lane * 8 + t];

    int myc = 0;
    #pragma unroll
    for (int t = 0; t < 8; t++) myc += __popc(w8[t]);

    int incl = myc;
    #pragma unroll
    for (int d = 1; d < 32; d <<= 1) {
        int u = __shfl_up_sync(FULLMASK, incl, d);
        if (lane >= d) incl += u;
    }
    int p = srowoff[warp] + incl - myc;

    const float fi = (float)i;
    float* __restrict__ outI = out;
    float* __restrict__ outJ = out + MAX_PAIRS;
    float* __restrict__ outW = out + 2 * MAX_PAIRS;
    float* __restrict__ outV = out + 3 * MAX_PAIRS;

    #pragma unroll
    for (int t = 0; t < 8; t++) {
        unsigned word = w8[t];
        const int jbase = (lane * 8 + t) * 32;
        while (word) {
            const int bpos = __ffs(word) - 1;
            word &= word - 1;
            const int j = jbase + bpos;
            const float dx = pix - pos[3 * j + 0];
            const float dy = piy - pos[3 * j + 1];
            const float dz = piz - pos[3 * j + 2];
            const float d2 = d2_exact(dx, dy, dz);
            if (p < MAX_PAIRS) {
                outI[p] = fi;
                outJ[p] = (float)j;
                outW[p] = sqrtf(d2);
                outV[3 * p + 0] = dx;
                outV[3 * p + 1] = dy;
                outV[3 * p + 2] = dz;
            }
            p++;
        }
    }
}

// ---------------------------------------------------------------------------
// K3: vectorized tail fill + scratch restore.
// Invalid tail [total, MAX_PAIRS): index=-1, weight=0, vec=0.
// 4 slots per thread via float4 stores; one thread handles the <=3
// unaligned boundary slots. Also restores g_cell_cnt/g_state to zero.
// ---------------------------------------------------------------------------
__global__ void tailfix_kernel(float* __restrict__ out) {
    // scratch restore (disjoint blocks; no ordering hazards within this kernel)
    if (blockIdx.x == 0) {
        for (int k = threadIdx.x; k < NCELLS; k += blockDim.x) g_cell_cnt[k] = 0;
    } else if (blockIdx.x == 1) {
        for (int k = threadIdx.x; k < NBLK; k += blockDim.x) g_state[k] = 0u;
    }

    int total = g_total;
    if (total > MAX_PAIRS) total = MAX_PAIRS;
    const int aligned = (total + 3) & ~3;

    const int gid = blockIdx.x * blockDim.x + threadIdx.x;

    // boundary scalars [total, aligned)
    if (gid == 0) {
        for (int p = total; p < aligned && p < MAX_PAIRS; p++) {
            out[p]                 = -1.0f;
            out[MAX_PAIRS + p]     = -1.0f;
            out[2 * MAX_PAIRS + p] = 0.0f;
            float* v = out + 3 * MAX_PAIRS + 3 * p;
            v[0] = 0.0f; v[1] = 0.0f; v[2] = 0.0f;
        }
    }

    // vector part: 4 slots per thread starting at 'aligned'
    const int p4 = aligned + gid * 4;
    if (p4 >= MAX_PAIRS) return;

    const float4 neg1 = make_float4(-1.0f, -1.0f, -1.0f, -1.0f);
    const float4 zero = make_float4(0.0f, 0.0f, 0.0f, 0.0f);

    *reinterpret_cast<float4*>(out + p4)                 = neg1;  // i
    *reinterpret_cast<float4*>(out + MAX_PAIRS + p4)     = neg1;  // j
    *reinterpret_cast<float4*>(out + 2 * MAX_PAIRS + p4) = zero;  // w
    float4* v4 = reinterpret_cast<float4*>(out + 3 * MAX_PAIRS + 3 * p4);
    v4[0] = zero; v4[1] = zero; v4[2] = zero;                      // vec (12 f)
}

// ---------------------------------------------------------------------------
extern "C" void kernel_launch(void* const* d_in, const int* in_sizes, int n_in,
                              void* d_out, int out_size) {
    const float* pos   = (const float*)d_in[0];   // [8192, 3] f32
    const int*   batch = (const int*)d_in[1];     // [8192] i32
    float* out = (float*)d_out;                   // 6 * MAX_PAIRS floats

    (void)in_sizes; (void)n_in; (void)out_size;

    build_kernel<<<NATOMS / 64, 64>>>(pos, batch);
    pairs_kernel<<<NBLK, 256>>>(pos, batch, out);
    tailfix_kernel<<<MAX_PAIRS / 4 / 256, 256>>>(out);
}